// round 15
// baseline (speedup 1.0000x reference)
#include <cuda_runtime.h>
#include <cstdint>

#define S_LEN 4096
#define HID   768
#define NH    12
#define HD    64

typedef unsigned long long u64;

__device__ __forceinline__ u64 pk2(float lo, float hi) {
    u64 r; asm("mov.b64 %0, {%1, %2};" : "=l"(r) : "f"(lo), "f"(hi)); return r;
}
__device__ __forceinline__ float ex2f(float x) {
    float r; asm("ex2.approx.f32 %0, %1;" : "=f"(r) : "f"(x)); return r;
}
__device__ __forceinline__ uint32_t to_tf32(float f) {
    uint32_t r; asm("cvt.rna.tf32.f32 %0, %1;" : "=r"(r) : "f"(f)); return r;
}
// HMMA: D(16x8,f32) += A(16x8,tf32) * B(8x8,tf32)   (row.col)
__device__ __forceinline__ void mma8(float* d, const uint32_t* a, uint32_t b0, uint32_t b1) {
    asm volatile("mma.sync.aligned.m16n8k8.row.col.f32.tf32.tf32.f32 "
        "{%0,%1,%2,%3}, {%4,%5,%6,%7}, {%8,%9}, {%0,%1,%2,%3};"
        : "+f"(d[0]), "+f"(d[1]), "+f"(d[2]), "+f"(d[3])
        : "r"(a[0]), "r"(a[1]), "r"(a[2]), "r"(a[3]), "r"(b0), "r"(b1));
}
__device__ __forceinline__ void ldsm4(uint32_t& r0, uint32_t& r1, uint32_t& r2,
                                      uint32_t& r3, uint32_t addr) {
    asm volatile("ldmatrix.sync.aligned.m8n8.x4.shared.b16 {%0,%1,%2,%3}, [%4];"
        : "=r"(r0), "=r"(r1), "=r"(r2), "=r"(r3) : "r"(addr));
}
__device__ __forceinline__ uint32_t smem_to_u32(const void* p) {
    uint32_t a;
    asm("{ .reg .u64 t; cvta.to.shared.u64 t, %1; cvt.u32.u64 %0, t; }" : "=r"(a) : "l"(p));
    return a;
}
__device__ __forceinline__ void cpa16(uint32_t dst, const void* src) {
    asm volatile("cp.async.ca.shared.global [%0], [%1], 16;" :: "r"(dst), "l"(src));
}
#define CP_COMMIT() asm volatile("cp.async.commit_group;" ::: "memory")
#define CP_WAIT1()  asm volatile("cp.async.wait_group 1;" ::: "memory")
#define CP_WAIT0()  asm volatile("cp.async.wait_group 0;" ::: "memory")

#define NSPLIT 2
#define KTILE 32
#define KV_TILES (S_LEN / NSPLIT / KTILE)    /* 64 tiles of 32 per split */

// Scratch
__device__ float g_Q [NH * S_LEN * HD];   // pre-scaled by 0.125*log2e, tf32
__device__ float g_K [NH * S_LEN * HD];   // [head][s][d], tf32
__device__ float g_Vt[NH * HD * S_LEN];   // [head][d][s], tf32  (TRANSPOSED)
__device__ float g_Xr[S_LEN * HID];
__device__ float g_Wr[3 * HID * HID];
__device__ float g_Op[NSPLIT * NH * S_LEN * HD];  // partial O (unnormalized)
__device__ float g_Lp[NSPLIT * NH * S_LEN];       // partial row sums

// ---------------------------------------------------------------------------
// Kernel 0: round X and W to tf32 (rna) once.
// ---------------------------------------------------------------------------
#define NX4 (S_LEN * HID / 4)
#define NW4 (HID * HID / 4)
#define TOT4 (NX4 + 3 * NW4)

__global__ void preround(const float* __restrict__ X,
                         const float* __restrict__ Wq,
                         const float* __restrict__ Wk,
                         const float* __restrict__ Wv)
{
    int i4 = blockIdx.x * blockDim.x + threadIdx.x;
    if (i4 >= TOT4) return;
    float4 v; float4* dst;
    if (i4 < NX4) {
        v = ((const float4*)X)[i4];
        dst = &((float4*)g_Xr)[i4];
    } else {
        int j = i4 - NX4;
        int w = j / NW4, k = j - w * NW4;
        const float* src = (w == 0) ? Wq : (w == 1) ? Wk : Wv;
        v = ((const float4*)src)[k];
        dst = &((float4*)g_Wr)[w * NW4 + k];
    }
    float4 r;
    r.x = __uint_as_float(to_tf32(v.x));
    r.y = __uint_as_float(to_tf32(v.y));
    r.z = __uint_as_float(to_tf32(v.z));
    r.w = __uint_as_float(to_tf32(v.w));
    *dst = r;
}

// ---------------------------------------------------------------------------
// Kernel 1: QKV projection, tf32 mma.sync, cp.async double-buffered.
// Grid (12, 32, 3). CTA tile 128(M) x 64(N), BK=32.
// z==0: Q scaled by 0.125*log2e.  z==2: V transposed in-smem, g_Vt coalesced.
// ---------------------------------------------------------------------------
#define XP 36
#define WP 72
#define TRP 132
#define QSCALE 0.1803368801111204f   /* 0.125 * log2(e) */
#define SH_X (2 * 128 * XP)
#define SH_W (2 * 32 * WP)

__global__ __launch_bounds__(128, 4) void qkv_mma(
    const float* __restrict__ bq, const float* __restrict__ bk,
    const float* __restrict__ bv)
{
    __shared__ uint32_t shbuf[SH_X + SH_W];
    const uint32_t SX = smem_to_u32(shbuf);
    const uint32_t SW = SX + 4 * SH_X;
    uint32_t* Ws0 = shbuf + SH_X;

    const int z = blockIdx.z;
    const int row0 = blockIdx.y * 128;
    const int col0 = blockIdx.x * 64;
    const int tid = threadIdx.x;
    const int wid = tid >> 5, lane = tid & 31;
    const int g = lane >> 2, tig = lane & 3;
    const int warp_row = wid * 32;
    const int rowA = (lane & 7) + 8 * ((lane >> 3) & 1);
    const int colA = ((lane >> 4) & 1) * 4;

    const float* Xsrc = g_Xr + row0 * HID;
    const float* Wsrc = g_Wr + z * (HID * HID) + col0;

    float acc[2][8][4];
    #pragma unroll
    for (int mt = 0; mt < 2; mt++)
        #pragma unroll
        for (int nt = 0; nt < 8; nt++)
            #pragma unroll
            for (int f = 0; f < 4; f++) acc[mt][nt][f] = 0.0f;

    {
        #pragma unroll
        for (int it = 0; it < 8; it++) {
            int idx = tid + it * 128;
            int r = idx >> 3, c4 = (idx & 7) << 2;
            cpa16(SX + 4 * (r * XP + c4), Xsrc + r * HID + c4);
        }
        #pragma unroll
        for (int it = 0; it < 4; it++) {
            int idx = tid + it * 128;
            int r = idx >> 4, c4 = (idx & 15) << 2;
            cpa16(SW + 4 * (r * WP + c4), Wsrc + r * HID + c4);
        }
        CP_COMMIT();
    }

    for (int c = 0; c < 24; c++) {
        const int s = c & 1;
        __syncthreads();
        if (c < 23) {
            const int k0 = (c + 1) * 32;
            #pragma unroll
            for (int it = 0; it < 8; it++) {
                int idx = tid + it * 128;
                int r = idx >> 3, c4 = (idx & 7) << 2;
                cpa16(SX + 4 * ((s ^ 1) * 128 * XP + r * XP + c4),
                      Xsrc + r * HID + k0 + c4);
            }
            #pragma unroll
            for (int it = 0; it < 4; it++) {
                int idx = tid + it * 128;
                int r = idx >> 4, c4 = (idx & 15) << 2;
                cpa16(SW + 4 * ((s ^ 1) * 32 * WP + r * WP + c4),
                      Wsrc + (k0 + r) * HID + c4);
            }
            CP_COMMIT();
            CP_WAIT1();
        } else {
            CP_WAIT0();
        }
        __syncthreads();

        const uint32_t xb = SX + 4 * (s * 128 * XP + (warp_row + rowA) * XP + colA);
        #pragma unroll
        for (int kt = 0; kt < 4; kt++) {
            uint32_t a0[4], a1[4];
            ldsm4(a0[0], a0[1], a0[2], a0[3], xb + kt * 32);
            ldsm4(a1[0], a1[1], a1[2], a1[3], xb + 16 * XP * 4 + kt * 32);
            const uint32_t* ws = Ws0 + s * 32 * WP + kt * 8 * WP;
            #pragma unroll
            for (int nt = 0; nt < 8; nt++) {
                uint32_t b0 = ws[tig * WP + nt * 8 + g];
                uint32_t b1 = ws[(tig + 4) * WP + nt * 8 + g];
                mma8(acc[0][nt], a0, b0, b1);
                mma8(acc[1][nt], a1, b0, b1);
            }
        }
    }

    const float* bias = (z == 0) ? bq : (z == 1) ? bk : bv;
    const int head = blockIdx.x;

    if (z == 2) {
        __syncthreads();
        uint32_t* Tr = shbuf;                // 64 x 132 words
        #pragma unroll
        for (int mt = 0; mt < 2; mt++) {
            int ls = warp_row + mt * 16 + g;
            #pragma unroll
            for (int nt = 0; nt < 8; nt++) {
                int d = nt * 8 + 2 * tig;
                float b0 = bias[col0 + d], b1 = bias[col0 + d + 1];
                Tr[d * TRP + ls]           = to_tf32(acc[mt][nt][0] + b0);
                Tr[(d + 1) * TRP + ls]     = to_tf32(acc[mt][nt][1] + b1);
                Tr[d * TRP + ls + 8]       = to_tf32(acc[mt][nt][2] + b0);
                Tr[(d + 1) * TRP + ls + 8] = to_tf32(acc[mt][nt][3] + b1);
            }
        }
        __syncthreads();
        float* vt = g_Vt + head * (HD * S_LEN) + row0;
        #pragma unroll
        for (int it = 0; it < 16; it++) {
            int idx4 = tid + it * 128;
            int d = idx4 >> 5, c4 = (idx4 & 31) << 2;
            uint4 v = make_uint4(Tr[d * TRP + c4],     Tr[d * TRP + c4 + 1],
                                 Tr[d * TRP + c4 + 2], Tr[d * TRP + c4 + 3]);
            *(uint4*)&vt[d * S_LEN + c4] = v;
        }
    } else {
        float* outp = (z == 0) ? g_Q : g_K;
        const float scale = (z == 0) ? QSCALE : 1.0f;
        #pragma unroll
        for (int mt = 0; mt < 2; mt++) {
            int r0 = row0 + warp_row + mt * 16 + g;
            #pragma unroll
            for (int nt = 0; nt < 8; nt++) {
                int d = nt * 8 + 2 * tig;
                float b0 = bias[col0 + d], b1 = bias[col0 + d + 1];
                float2 lo = make_float2(
                    __uint_as_float(to_tf32((acc[mt][nt][0] + b0) * scale)),
                    __uint_as_float(to_tf32((acc[mt][nt][1] + b1) * scale)));
                float2 hi = make_float2(
                    __uint_as_float(to_tf32((acc[mt][nt][2] + b0) * scale)),
                    __uint_as_float(to_tf32((acc[mt][nt][3] + b1) * scale)));
                *(float2*)&outp[(head * S_LEN + r0) * HD + d] = lo;
                *(float2*)&outp[(head * S_LEN + r0 + 8) * HD + d] = hi;
            }
        }
    }
}

// ---------------------------------------------------------------------------
// Kernel 2: flash attention, split-KV, KV tile 32, 3-STAGE ring (prefetch
// distance 2), 3 CTA/SM. Grid (32, 12, NSPLIT). Warp owns 32 q-rows.
// Smem (words): K 3x[32][68] | Vt 3x[64][36] | P 4x[32][36]  = 72.2 KB
// P stored as RAW fp32 (tf32 MMA truncates in HW; no cvt on critical path).
// ---------------------------------------------------------------------------
#define PKF 68
#define PVF 36
#define KSTG (KTILE * PKF)          /* 2176 */
#define VSTG (64 * PVF)             /* 2304 */
#define KS_OFF 0
#define VS_OFF (3 * KSTG)           /* 6528 */
#define PS_OFF (VS_OFF + 3 * VSTG)  /* 13440 */
#define PS_WARP (32 * PVF)          /* 1152 */
#define SMEM_WORDS (PS_OFF + 4 * PS_WARP)   /* 18048 */
#define FLASH_SMEM (SMEM_WORDS * 4)          /* 72192 B -> 3 CTA/SM */

__device__ __forceinline__ void stage_kv(uint32_t S, const float* Kg, const float* Vtg,
                                         int kbase, int s, int tid) {
    #pragma unroll
    for (int it = 0; it < 4; it++) {          // K: 32 x 64
        int idx4 = tid + it * 128;
        int r = idx4 >> 4, c4 = (idx4 & 15) << 2;
        cpa16(S + 4 * (KS_OFF + s * KSTG + r * PKF + c4), Kg + (kbase + r) * HD + c4);
    }
    #pragma unroll
    for (int it = 0; it < 4; it++) {          // Vt: 64 x 32
        int idx4 = tid + it * 128;
        int d = idx4 >> 3, c4 = (idx4 & 7) << 2;
        cpa16(S + 4 * (VS_OFF + s * VSTG + d * PVF + c4), Vtg + d * S_LEN + kbase + c4);
    }
}

__global__ __launch_bounds__(128, 3) void flash_attn()
{
    extern __shared__ uint32_t sm[];
    const uint32_t S = smem_to_u32(sm);

    const int head  = blockIdx.y;
    const int q0    = blockIdx.x * 128;
    const int split = blockIdx.z;
    const int kv0   = split * (S_LEN / NSPLIT);
    const int tid  = threadIdx.x;
    const int wid  = tid >> 5;
    const int lane = tid & 31;
    const int g    = lane >> 2;
    const int tig  = lane & 3;
    const int warp_row = wid * 32;

    const float* Qg  = g_Q  + (head * S_LEN + q0) * HD;
    const float* Kg  = g_K  + head * S_LEN * HD;
    const float* Vtg = g_Vt + head * (HD * S_LEN);

    const int rowA = (lane & 7) + 8 * ((lane >> 3) & 1);
    const int colA = ((lane >> 4) & 1) * 4;
    const int rowB = (lane & 7) + 8 * ((lane >> 4) & 1);
    const int colB = ((lane >> 3) & 1) * 4;

    const uint32_t aP0 = S + 4 * (PS_OFF + wid * PS_WARP + rowA * PVF + colA);
    const uint32_t aP1 = aP0 + 4 * (16 * PVF);
    const uint32_t bKbase = S + 4 * (KS_OFF + rowB * PKF + colB);
    const uint32_t bVbase = S + 4 * (VS_OFF + rowB * PVF + colB);

    // prologue: Q (128x64, pitch 68) staged at offset 0 (overlaps KV region)
    #pragma unroll
    for (int it = 0; it < 16; it++) {
        int idx4 = tid + it * 128;
        int r = idx4 >> 4, c4 = (idx4 & 15) << 2;
        cpa16(S + 4 * (r * PKF + c4), Qg + r * HD + c4);
    }
    CP_COMMIT();
    CP_WAIT0();
    __syncthreads();

    uint32_t qa[2][8][4];
    {
        const uint32_t aQ0 = S + 4 * ((warp_row + rowA) * PKF + colA);
        #pragma unroll
        for (int mt = 0; mt < 2; mt++) {
            const uint32_t aQ = aQ0 + mt * (16 * PKF * 4);
            #pragma unroll
            for (int kt = 0; kt < 8; kt++)
                ldsm4(qa[mt][kt][0], qa[mt][kt][1], qa[mt][kt][2], qa[mt][kt][3],
                      aQ + kt * 32);
        }
    }
    __syncthreads();               // everyone done reading Q before overwrite
    stage_kv(S, Kg, Vtg, kv0, 0, tid);
    CP_COMMIT();
    stage_kv(S, Kg, Vtg, kv0 + KTILE, 1, tid);
    CP_COMMIT();

    float oacc[2][8][4];
    float lsum[2][2];
    #pragma unroll
    for (int mt = 0; mt < 2; mt++) {
        lsum[mt][0] = 0.0f; lsum[mt][1] = 0.0f;
        #pragma unroll
        for (int nt = 0; nt < 8; nt++)
            #pragma unroll
            for (int f = 0; f < 4; f++) oacc[mt][nt][f] = 0.0f;
    }

    uint32_t* Ps = &sm[PS_OFF + wid * PS_WARP];

    int sl = 0;                     // compute slot = t % 3
    int sp = 2;                     // prefetch slot = (t+2) % 3
    for (int t = 0; t < KV_TILES; t++) {
        if (t + 1 < KV_TILES) { CP_WAIT1(); } else { CP_WAIT0(); }
        __syncthreads();
        if (t + 2 < KV_TILES) {
            stage_kv(S, Kg, Vtg, kv0 + (t + 2) * KTILE, sp, tid);
            CP_COMMIT();
        }

        // ---- MMA1: Y(32x32) = Q @ K^T ----
        float sacc[2][4][4];
        #pragma unroll
        for (int mt = 0; mt < 2; mt++)
            #pragma unroll
            for (int nt = 0; nt < 4; nt++)
                #pragma unroll
                for (int f = 0; f < 4; f++) sacc[mt][nt][f] = 0.0f;

        const uint32_t bK = bKbase + 4 * sl * KSTG;
        #pragma unroll
        for (int kt = 0; kt < 8; kt++) {
            #pragma unroll
            for (int np = 0; np < 2; np++) {
                uint32_t b0, b1, b2, b3;
                ldsm4(b0, b1, b2, b3, bK + np * (16 * PKF * 4) + kt * 32);
                mma8(sacc[0][2 * np],     qa[0][kt], b0, b1);
                mma8(sacc[0][2 * np + 1], qa[0][kt], b2, b3);
                mma8(sacc[1][2 * np],     qa[1][kt], b0, b1);
                mma8(sacc[1][2 * np + 1], qa[1][kt], b2, b3);
            }
        }

        // ---- softmax: P = 2^Y via MUFU; row sums; stage P RAW fp32 ----
        #pragma unroll
        for (int mt = 0; mt < 2; mt++) {
            #pragma unroll
            for (int nt = 0; nt < 4; nt++) {
                float e0 = ex2f(sacc[mt][nt][0]);
                float e1 = ex2f(sacc[mt][nt][1]);
                float e2 = ex2f(sacc[mt][nt][2]);
                float e3 = ex2f(sacc[mt][nt][3]);
                lsum[mt][0] += e0 + e1;
                lsum[mt][1] += e2 + e3;
                *(u64*)&Ps[(mt * 16 + g) * PVF + nt * 8 + 2 * tig] = pk2(e0, e1);
                *(u64*)&Ps[(mt * 16 + g + 8) * PVF + nt * 8 + 2 * tig] = pk2(e2, e3);
            }
        }
        __syncwarp();

        // ---- MMA2: O(32x64) += P(32x32) @ V(32x64) ----
        const uint32_t bV = bVbase + 4 * sl * VSTG;
        #pragma unroll
        for (int kt = 0; kt < 4; kt++) {
            uint32_t pa0[4], pa1[4];
            ldsm4(pa0[0], pa0[1], pa0[2], pa0[3], aP0 + kt * 32);
            ldsm4(pa1[0], pa1[1], pa1[2], pa1[3], aP1 + kt * 32);
            #pragma unroll
            for (int np = 0; np < 4; np++) {
                uint32_t b0, b1, b2, b3;
                ldsm4(b0, b1, b2, b3, bV + np * (16 * PVF * 4) + kt * 32);
                mma8(oacc[0][2 * np],     pa0, b0, b1);
                mma8(oacc[0][2 * np + 1], pa0, b2, b3);
                mma8(oacc[1][2 * np],     pa1, b0, b1);
                mma8(oacc[1][2 * np + 1], pa1, b2, b3);
            }
        }

        if (++sl == 3) sl = 0;
        if (++sp == 3) sp = 0;
    }

    // quad reduction; write UNNORMALIZED partial O and row sums
    float* Op = g_Op + (split * NH + head) * (S_LEN * HD);
    float* Lp = g_Lp + (split * NH + head) * S_LEN;
    #pragma unroll
    for (int mt = 0; mt < 2; mt++) {
        #pragma unroll
        for (int h = 0; h < 2; h++) {
            float v = lsum[mt][h];
            v += __shfl_xor_sync(0xffffffffu, v, 1);
            v += __shfl_xor_sync(0xffffffffu, v, 2);
            lsum[mt][h] = v;
        }
        const int r0 = q0 + warp_row + mt * 16 + g;
        if (tig == 0) {
            Lp[r0]     = lsum[mt][0];
            Lp[r0 + 8] = lsum[mt][1];
        }
        #pragma unroll
        for (int nt = 0; nt < 8; nt++) {
            int col = nt * 8 + 2 * tig;
            *(float2*)&Op[r0 * HD + col] =
                make_float2(oacc[mt][nt][0], oacc[mt][nt][1]);
            *(float2*)&Op[(r0 + 8) * HD + col] =
                make_float2(oacc[mt][nt][2], oacc[mt][nt][3]);
        }
    }
}

// ---------------------------------------------------------------------------
// Kernel 3: combine splits.  out[q][h*64+d] = (O0+O1) / (l0+l1)
// ---------------------------------------------------------------------------
#define CTOT (NH * S_LEN * HD / 4)

__global__ void combine(float* __restrict__ out)
{
    int i4 = blockIdx.x * blockDim.x + threadIdx.x;
    if (i4 >= CTOT) return;
    int d4 = (i4 & 15) << 2;
    int q  = (i4 >> 4) & (S_LEN - 1);
    int h  = i4 >> 16;

    float4 a = ((const float4*)g_Op)[i4];
    float4 b = ((const float4*)(g_Op + NH * S_LEN * HD))[i4];
    float l = g_Lp[h * S_LEN + q] + g_Lp[NH * S_LEN + h * S_LEN + q];
    float inv = 1.0f / l;
    float4 r = make_float4((a.x + b.x) * inv, (a.y + b.y) * inv,
                           (a.z + b.z) * inv, (a.w + b.w) * inv);
    *(float4*)&out[q * HID + h * HD + d4] = r;
}

// ---------------------------------------------------------------------------
extern "C" void kernel_launch(void* const* d_in, const int* in_sizes, int n_in,
                              void* d_out, int out_size)
{
    const float* X  = (const float*)d_in[0];
    const float* Wq = (const float*)d_in[1];
    const float* bq = (const float*)d_in[2];
    const float* Wk = (const float*)d_in[3];
    const float* bk = (const float*)d_in[4];
    const float* Wv = (const float*)d_in[5];
    const float* bv = (const float*)d_in[6];
    float* out = (float*)d_out;

    cudaFuncSetAttribute(flash_attn, cudaFuncAttributeMaxDynamicSharedMemorySize,
                         (int)FLASH_SMEM);

    preround<<<(TOT4 + 255) / 256, 256>>>(X, Wq, Wk, Wv);

    dim3 g1(HID / 64, S_LEN / 128, 3);
    qkv_mma<<<g1, 128>>>(bq, bk, bv);

    dim3 g2(S_LEN / 128, NH, NSPLIT);
    flash_attn<<<g2, 128, FLASH_SMEM>>>();

    combine<<<(CTOT + 255) / 256, 256>>>(out);
}

// round 16
// speedup vs baseline: 1.1726x; 1.1726x over previous
#include <cuda_runtime.h>
#include <cstdint>

#define S_LEN 4096
#define HID   768
#define NH    12
#define HD    64

typedef unsigned long long u64;

__device__ __forceinline__ u64 pk2(float lo, float hi) {
    u64 r; asm("mov.b64 %0, {%1, %2};" : "=l"(r) : "f"(lo), "f"(hi)); return r;
}
__device__ __forceinline__ float ex2f(float x) {
    float r; asm("ex2.approx.f32 %0, %1;" : "=f"(r) : "f"(x)); return r;
}
__device__ __forceinline__ uint32_t to_tf32(float f) {
    uint32_t r; asm("cvt.rna.tf32.f32 %0, %1;" : "=r"(r) : "f"(f)); return r;
}
// HMMA: D(16x8,f32) += A(16x8,tf32) * B(8x8,tf32)   (row.col)
__device__ __forceinline__ void mma8(float* d, const uint32_t* a, uint32_t b0, uint32_t b1) {
    asm volatile("mma.sync.aligned.m16n8k8.row.col.f32.tf32.tf32.f32 "
        "{%0,%1,%2,%3}, {%4,%5,%6,%7}, {%8,%9}, {%0,%1,%2,%3};"
        : "+f"(d[0]), "+f"(d[1]), "+f"(d[2]), "+f"(d[3])
        : "r"(a[0]), "r"(a[1]), "r"(a[2]), "r"(a[3]), "r"(b0), "r"(b1));
}
__device__ __forceinline__ void ldsm4(uint32_t& r0, uint32_t& r1, uint32_t& r2,
                                      uint32_t& r3, uint32_t addr) {
    asm volatile("ldmatrix.sync.aligned.m8n8.x4.shared.b16 {%0,%1,%2,%3}, [%4];"
        : "=r"(r0), "=r"(r1), "=r"(r2), "=r"(r3) : "r"(addr));
}
__device__ __forceinline__ uint32_t smem_to_u32(const void* p) {
    uint32_t a;
    asm("{ .reg .u64 t; cvta.to.shared.u64 t, %1; cvt.u32.u64 %0, t; }" : "=r"(a) : "l"(p));
    return a;
}
__device__ __forceinline__ void cpa16(uint32_t dst, const void* src) {
    asm volatile("cp.async.ca.shared.global [%0], [%1], 16;" :: "r"(dst), "l"(src));
}
#define CP_COMMIT() asm volatile("cp.async.commit_group;" ::: "memory")
#define CP_WAIT1()  asm volatile("cp.async.wait_group 1;" ::: "memory")
#define CP_WAIT0()  asm volatile("cp.async.wait_group 0;" ::: "memory")

#define NSPLIT 2
#define KTILE 32
#define KV_TILES (S_LEN / NSPLIT / KTILE)    /* 64 tiles of 32 per split */

// Scratch
__device__ float g_Q [NH * S_LEN * HD];   // pre-scaled by 0.125*log2e, tf32
__device__ float g_K [NH * S_LEN * HD];   // [head][s][d], tf32
__device__ float g_Vt[NH * HD * S_LEN];   // [head][d][s], tf32  (TRANSPOSED)
__device__ float g_Xr[S_LEN * HID];
__device__ float g_Wr[3 * HID * HID];
__device__ float g_Op[NSPLIT * NH * S_LEN * HD];  // partial O (unnormalized)
__device__ float g_Lp[NSPLIT * NH * S_LEN];       // partial row sums

// ---------------------------------------------------------------------------
// Kernel 0: round X and W to tf32 (rna) once.
// ---------------------------------------------------------------------------
#define NX4 (S_LEN * HID / 4)
#define NW4 (HID * HID / 4)
#define TOT4 (NX4 + 3 * NW4)

__global__ void preround(const float* __restrict__ X,
                         const float* __restrict__ Wq,
                         const float* __restrict__ Wk,
                         const float* __restrict__ Wv)
{
    int i4 = blockIdx.x * blockDim.x + threadIdx.x;
    if (i4 >= TOT4) return;
    float4 v; float4* dst;
    if (i4 < NX4) {
        v = ((const float4*)X)[i4];
        dst = &((float4*)g_Xr)[i4];
    } else {
        int j = i4 - NX4;
        int w = j / NW4, k = j - w * NW4;
        const float* src = (w == 0) ? Wq : (w == 1) ? Wk : Wv;
        v = ((const float4*)src)[k];
        dst = &((float4*)g_Wr)[w * NW4 + k];
    }
    float4 r;
    r.x = __uint_as_float(to_tf32(v.x));
    r.y = __uint_as_float(to_tf32(v.y));
    r.z = __uint_as_float(to_tf32(v.z));
    r.w = __uint_as_float(to_tf32(v.w));
    *dst = r;
}

// ---------------------------------------------------------------------------
// Kernel 1: QKV projection, tf32 mma.sync, cp.async double-buffered.
// Grid (12, 32, 3). CTA tile 128(M) x 64(N), BK=32.
// z==0: Q scaled by 0.125*log2e.  z==2: V transposed in-smem, g_Vt coalesced.
// ---------------------------------------------------------------------------
#define XP 36
#define WP 72
#define TRP 132
#define QSCALE 0.1803368801111204f   /* 0.125 * log2(e) */
#define SH_X (2 * 128 * XP)
#define SH_W (2 * 32 * WP)

__global__ __launch_bounds__(128, 4) void qkv_mma(
    const float* __restrict__ bq, const float* __restrict__ bk,
    const float* __restrict__ bv)
{
    __shared__ uint32_t shbuf[SH_X + SH_W];
    const uint32_t SX = smem_to_u32(shbuf);
    const uint32_t SW = SX + 4 * SH_X;
    uint32_t* Ws0 = shbuf + SH_X;

    const int z = blockIdx.z;
    const int row0 = blockIdx.y * 128;
    const int col0 = blockIdx.x * 64;
    const int tid = threadIdx.x;
    const int wid = tid >> 5, lane = tid & 31;
    const int g = lane >> 2, tig = lane & 3;
    const int warp_row = wid * 32;
    const int rowA = (lane & 7) + 8 * ((lane >> 3) & 1);
    const int colA = ((lane >> 4) & 1) * 4;

    const float* Xsrc = g_Xr + row0 * HID;
    const float* Wsrc = g_Wr + z * (HID * HID) + col0;

    float acc[2][8][4];
    #pragma unroll
    for (int mt = 0; mt < 2; mt++)
        #pragma unroll
        for (int nt = 0; nt < 8; nt++)
            #pragma unroll
            for (int f = 0; f < 4; f++) acc[mt][nt][f] = 0.0f;

    {
        #pragma unroll
        for (int it = 0; it < 8; it++) {
            int idx = tid + it * 128;
            int r = idx >> 3, c4 = (idx & 7) << 2;
            cpa16(SX + 4 * (r * XP + c4), Xsrc + r * HID + c4);
        }
        #pragma unroll
        for (int it = 0; it < 4; it++) {
            int idx = tid + it * 128;
            int r = idx >> 4, c4 = (idx & 15) << 2;
            cpa16(SW + 4 * (r * WP + c4), Wsrc + r * HID + c4);
        }
        CP_COMMIT();
    }

    for (int c = 0; c < 24; c++) {
        const int s = c & 1;
        __syncthreads();
        if (c < 23) {
            const int k0 = (c + 1) * 32;
            #pragma unroll
            for (int it = 0; it < 8; it++) {
                int idx = tid + it * 128;
                int r = idx >> 3, c4 = (idx & 7) << 2;
                cpa16(SX + 4 * ((s ^ 1) * 128 * XP + r * XP + c4),
                      Xsrc + r * HID + k0 + c4);
            }
            #pragma unroll
            for (int it = 0; it < 4; it++) {
                int idx = tid + it * 128;
                int r = idx >> 4, c4 = (idx & 15) << 2;
                cpa16(SW + 4 * ((s ^ 1) * 32 * WP + r * WP + c4),
                      Wsrc + (k0 + r) * HID + c4);
            }
            CP_COMMIT();
            CP_WAIT1();
        } else {
            CP_WAIT0();
        }
        __syncthreads();

        const uint32_t xb = SX + 4 * (s * 128 * XP + (warp_row + rowA) * XP + colA);
        #pragma unroll
        for (int kt = 0; kt < 4; kt++) {
            uint32_t a0[4], a1[4];
            ldsm4(a0[0], a0[1], a0[2], a0[3], xb + kt * 32);
            ldsm4(a1[0], a1[1], a1[2], a1[3], xb + 16 * XP * 4 + kt * 32);
            const uint32_t* ws = Ws0 + s * 32 * WP + kt * 8 * WP;
            #pragma unroll
            for (int nt = 0; nt < 8; nt++) {
                uint32_t b0 = ws[tig * WP + nt * 8 + g];
                uint32_t b1 = ws[(tig + 4) * WP + nt * 8 + g];
                mma8(acc[0][nt], a0, b0, b1);
                mma8(acc[1][nt], a1, b0, b1);
            }
        }
    }

    const float* bias = (z == 0) ? bq : (z == 1) ? bk : bv;
    const int head = blockIdx.x;

    if (z == 2) {
        __syncthreads();
        uint32_t* Tr = shbuf;                // 64 x 132 words
        #pragma unroll
        for (int mt = 0; mt < 2; mt++) {
            int ls = warp_row + mt * 16 + g;
            #pragma unroll
            for (int nt = 0; nt < 8; nt++) {
                int d = nt * 8 + 2 * tig;
                float b0 = bias[col0 + d], b1 = bias[col0 + d + 1];
                Tr[d * TRP + ls]           = to_tf32(acc[mt][nt][0] + b0);
                Tr[(d + 1) * TRP + ls]     = to_tf32(acc[mt][nt][1] + b1);
                Tr[d * TRP + ls + 8]       = to_tf32(acc[mt][nt][2] + b0);
                Tr[(d + 1) * TRP + ls + 8] = to_tf32(acc[mt][nt][3] + b1);
            }
        }
        __syncthreads();
        float* vt = g_Vt + head * (HD * S_LEN) + row0;
        #pragma unroll
        for (int it = 0; it < 16; it++) {
            int idx4 = tid + it * 128;
            int d = idx4 >> 5, c4 = (idx4 & 31) << 2;
            uint4 v = make_uint4(Tr[d * TRP + c4],     Tr[d * TRP + c4 + 1],
                                 Tr[d * TRP + c4 + 2], Tr[d * TRP + c4 + 3]);
            *(uint4*)&vt[d * S_LEN + c4] = v;
        }
    } else {
        float* outp = (z == 0) ? g_Q : g_K;
        const float scale = (z == 0) ? QSCALE : 1.0f;
        #pragma unroll
        for (int mt = 0; mt < 2; mt++) {
            int r0 = row0 + warp_row + mt * 16 + g;
            #pragma unroll
            for (int nt = 0; nt < 8; nt++) {
                int d = nt * 8 + 2 * tig;
                float b0 = bias[col0 + d], b1 = bias[col0 + d + 1];
                float2 lo = make_float2(
                    __uint_as_float(to_tf32((acc[mt][nt][0] + b0) * scale)),
                    __uint_as_float(to_tf32((acc[mt][nt][1] + b1) * scale)));
                float2 hi = make_float2(
                    __uint_as_float(to_tf32((acc[mt][nt][2] + b0) * scale)),
                    __uint_as_float(to_tf32((acc[mt][nt][3] + b1) * scale)));
                *(float2*)&outp[(head * S_LEN + r0) * HD + d] = lo;
                *(float2*)&outp[(head * S_LEN + r0 + 8) * HD + d] = hi;
            }
        }
    }
}

// ---------------------------------------------------------------------------
// Kernel 2: flash attention, split-KV, KV tile 32, 2-stage ring, 3 CTA/SM.
// (R14 proven core; only change: P stored as RAW fp32 — tf32 MMA truncates
// in hardware, removing 32 cvt per warp-tile from the softmax->MMA2 chain.)
// Grid (32, 12, NSPLIT). CTA = 128 q-rows, 4 warps; warp owns 32 q-rows.
// Smem (words): K 2x[32][68] | Vt 2x[64][36] | P 4x[32][36]  = 54.3 KB
// ---------------------------------------------------------------------------
#define PKF 68
#define PVF 36
#define KSTG (KTILE * PKF)          /* 2176 */
#define VSTG (64 * PVF)             /* 2304 */
#define KS_OFF 0
#define VS_OFF (2 * KSTG)           /* 4352 */
#define PS_OFF (VS_OFF + 2 * VSTG)  /* 8960 */
#define PS_WARP (32 * PVF)          /* 1152 */
#define SMEM_WORDS (PS_OFF + 4 * PS_WARP)   /* 13568 */
#define FLASH_SMEM (SMEM_WORDS * 4)          /* 54272 B -> 3 CTA/SM */

__device__ __forceinline__ void stage_kv(uint32_t S, const float* Kg, const float* Vtg,
                                         int kbase, int s, int tid) {
    #pragma unroll
    for (int it = 0; it < 4; it++) {          // K: 32 x 64
        int idx4 = tid + it * 128;
        int r = idx4 >> 4, c4 = (idx4 & 15) << 2;
        cpa16(S + 4 * (KS_OFF + s * KSTG + r * PKF + c4), Kg + (kbase + r) * HD + c4);
    }
    #pragma unroll
    for (int it = 0; it < 4; it++) {          // Vt: 64 x 32
        int idx4 = tid + it * 128;
        int d = idx4 >> 3, c4 = (idx4 & 7) << 2;
        cpa16(S + 4 * (VS_OFF + s * VSTG + d * PVF + c4), Vtg + d * S_LEN + kbase + c4);
    }
}

__global__ __launch_bounds__(128, 3) void flash_attn()
{
    extern __shared__ uint32_t sm[];
    const uint32_t S = smem_to_u32(sm);

    const int head  = blockIdx.y;
    const int q0    = blockIdx.x * 128;
    const int split = blockIdx.z;
    const int kv0   = split * (S_LEN / NSPLIT);
    const int tid  = threadIdx.x;
    const int wid  = tid >> 5;
    const int lane = tid & 31;
    const int g    = lane >> 2;
    const int tig  = lane & 3;
    const int warp_row = wid * 32;

    const float* Qg  = g_Q  + (head * S_LEN + q0) * HD;
    const float* Kg  = g_K  + head * S_LEN * HD;
    const float* Vtg = g_Vt + head * (HD * S_LEN);

    const int rowA = (lane & 7) + 8 * ((lane >> 3) & 1);
    const int colA = ((lane >> 4) & 1) * 4;
    const int rowB = (lane & 7) + 8 * ((lane >> 4) & 1);
    const int colB = ((lane >> 3) & 1) * 4;

    const uint32_t aP0 = S + 4 * (PS_OFF + wid * PS_WARP + rowA * PVF + colA);
    const uint32_t aP1 = aP0 + 4 * (16 * PVF);
    const uint32_t bKbase = S + 4 * (KS_OFF + rowB * PKF + colB);
    const uint32_t bVbase = S + 4 * (VS_OFF + rowB * PVF + colB);

    // prologue: Q (128x64, pitch 68) staged at offset 0 (overlaps KV region)
    #pragma unroll
    for (int it = 0; it < 16; it++) {
        int idx4 = tid + it * 128;
        int r = idx4 >> 4, c4 = (idx4 & 15) << 2;
        cpa16(S + 4 * (r * PKF + c4), Qg + r * HD + c4);
    }
    CP_COMMIT();
    CP_WAIT0();
    __syncthreads();

    uint32_t qa[2][8][4];
    {
        const uint32_t aQ0 = S + 4 * ((warp_row + rowA) * PKF + colA);
        #pragma unroll
        for (int mt = 0; mt < 2; mt++) {
            const uint32_t aQ = aQ0 + mt * (16 * PKF * 4);
            #pragma unroll
            for (int kt = 0; kt < 8; kt++)
                ldsm4(qa[mt][kt][0], qa[mt][kt][1], qa[mt][kt][2], qa[mt][kt][3],
                      aQ + kt * 32);
        }
    }
    __syncthreads();               // everyone done reading Q before overwrite
    stage_kv(S, Kg, Vtg, kv0, 0, tid);
    CP_COMMIT();

    float oacc[2][8][4];
    float lsum[2][2];
    #pragma unroll
    for (int mt = 0; mt < 2; mt++) {
        lsum[mt][0] = 0.0f; lsum[mt][1] = 0.0f;
        #pragma unroll
        for (int nt = 0; nt < 8; nt++)
            #pragma unroll
            for (int f = 0; f < 4; f++) oacc[mt][nt][f] = 0.0f;
    }

    uint32_t* Ps = &sm[PS_OFF + wid * PS_WARP];

    for (int t = 0; t < KV_TILES; t++) {
        const int s = t & 1;
        CP_WAIT0();
        __syncthreads();
        if (t < KV_TILES - 1) {
            stage_kv(S, Kg, Vtg, kv0 + (t + 1) * KTILE, s ^ 1, tid);
            CP_COMMIT();
        }

        // ---- MMA1: Y(32x32) = Q @ K^T ----
        float sacc[2][4][4];
        #pragma unroll
        for (int mt = 0; mt < 2; mt++)
            #pragma unroll
            for (int nt = 0; nt < 4; nt++)
                #pragma unroll
                for (int f = 0; f < 4; f++) sacc[mt][nt][f] = 0.0f;

        const uint32_t bK = bKbase + 4 * s * KSTG;
        #pragma unroll
        for (int kt = 0; kt < 8; kt++) {
            #pragma unroll
            for (int np = 0; np < 2; np++) {
                uint32_t b0, b1, b2, b3;
                ldsm4(b0, b1, b2, b3, bK + np * (16 * PKF * 4) + kt * 32);
                mma8(sacc[0][2 * np],     qa[0][kt], b0, b1);
                mma8(sacc[0][2 * np + 1], qa[0][kt], b2, b3);
                mma8(sacc[1][2 * np],     qa[1][kt], b0, b1);
                mma8(sacc[1][2 * np + 1], qa[1][kt], b2, b3);
            }
        }

        // ---- softmax: P = 2^Y via MUFU; row sums; stage P RAW fp32 ----
        #pragma unroll
        for (int mt = 0; mt < 2; mt++) {
            #pragma unroll
            for (int nt = 0; nt < 4; nt++) {
                float e0 = ex2f(sacc[mt][nt][0]);
                float e1 = ex2f(sacc[mt][nt][1]);
                float e2 = ex2f(sacc[mt][nt][2]);
                float e3 = ex2f(sacc[mt][nt][3]);
                lsum[mt][0] += e0 + e1;
                lsum[mt][1] += e2 + e3;
                *(u64*)&Ps[(mt * 16 + g) * PVF + nt * 8 + 2 * tig] = pk2(e0, e1);
                *(u64*)&Ps[(mt * 16 + g + 8) * PVF + nt * 8 + 2 * tig] = pk2(e2, e3);
            }
        }
        __syncwarp();

        // ---- MMA2: O(32x64) += P(32x32) @ V(32x64) ----
        const uint32_t bV = bVbase + 4 * s * VSTG;
        #pragma unroll
        for (int kt = 0; kt < 4; kt++) {
            uint32_t pa0[4], pa1[4];
            ldsm4(pa0[0], pa0[1], pa0[2], pa0[3], aP0 + kt * 32);
            ldsm4(pa1[0], pa1[1], pa1[2], pa1[3], aP1 + kt * 32);
            #pragma unroll
            for (int np = 0; np < 4; np++) {
                uint32_t b0, b1, b2, b3;
                ldsm4(b0, b1, b2, b3, bV + np * (16 * PVF * 4) + kt * 32);
                mma8(oacc[0][2 * np],     pa0, b0, b1);
                mma8(oacc[0][2 * np + 1], pa0, b2, b3);
                mma8(oacc[1][2 * np],     pa1, b0, b1);
                mma8(oacc[1][2 * np + 1], pa1, b2, b3);
            }
        }
    }

    // quad reduction; write UNNORMALIZED partial O and row sums
    float* Op = g_Op + (split * NH + head) * (S_LEN * HD);
    float* Lp = g_Lp + (split * NH + head) * S_LEN;
    #pragma unroll
    for (int mt = 0; mt < 2; mt++) {
        #pragma unroll
        for (int h = 0; h < 2; h++) {
            float v = lsum[mt][h];
            v += __shfl_xor_sync(0xffffffffu, v, 1);
            v += __shfl_xor_sync(0xffffffffu, v, 2);
            lsum[mt][h] = v;
        }
        const int r0 = q0 + warp_row + mt * 16 + g;
        if (tig == 0) {
            Lp[r0]     = lsum[mt][0];
            Lp[r0 + 8] = lsum[mt][1];
        }
        #pragma unroll
        for (int nt = 0; nt < 8; nt++) {
            int col = nt * 8 + 2 * tig;
            *(float2*)&Op[r0 * HD + col] =
                make_float2(oacc[mt][nt][0], oacc[mt][nt][1]);
            *(float2*)&Op[(r0 + 8) * HD + col] =
                make_float2(oacc[mt][nt][2], oacc[mt][nt][3]);
        }
    }
}

// ---------------------------------------------------------------------------
// Kernel 3: combine splits.  out[q][h*64+d] = (O0+O1) / (l0+l1)
// ---------------------------------------------------------------------------
#define CTOT (NH * S_LEN * HD / 4)

__global__ void combine(float* __restrict__ out)
{
    int i4 = blockIdx.x * blockDim.x + threadIdx.x;
    if (i4 >= CTOT) return;
    int d4 = (i4 & 15) << 2;
    int q  = (i4 >> 4) & (S_LEN - 1);
    int h  = i4 >> 16;

    float4 a = ((const float4*)g_Op)[i4];
    float4 b = ((const float4*)(g_Op + NH * S_LEN * HD))[i4];
    float l = g_Lp[h * S_LEN + q] + g_Lp[NH * S_LEN + h * S_LEN + q];
    float inv = 1.0f / l;
    float4 r = make_float4((a.x + b.x) * inv, (a.y + b.y) * inv,
                           (a.z + b.z) * inv, (a.w + b.w) * inv);
    *(float4*)&out[q * HID + h * HD + d4] = r;
}

// ---------------------------------------------------------------------------
extern "C" void kernel_launch(void* const* d_in, const int* in_sizes, int n_in,
                              void* d_out, int out_size)
{
    const float* X  = (const float*)d_in[0];
    const float* Wq = (const float*)d_in[1];
    const float* bq = (const float*)d_in[2];
    const float* Wk = (const float*)d_in[3];
    const float* bk = (const float*)d_in[4];
    const float* Wv = (const float*)d_in[5];
    const float* bv = (const float*)d_in[6];
    float* out = (float*)d_out;

    cudaFuncSetAttribute(flash_attn, cudaFuncAttributeMaxDynamicSharedMemorySize,
                         (int)FLASH_SMEM);

    preround<<<(TOT4 + 255) / 256, 256>>>(X, Wq, Wk, Wv);

    dim3 g1(HID / 64, S_LEN / 128, 3);
    qkv_mma<<<g1, 128>>>(bq, bk, bv);

    dim3 g2(S_LEN / 128, NH, NSPLIT);
    flash_attn<<<g2, 128, FLASH_SMEM>>>();

    combine<<<(CTOT + 255) / 256, 256>>>(out);
}